// round 10
// baseline (speedup 1.0000x reference)
#include <cuda_runtime.h>
#include <cstdint>
#include <math.h>

#define Bq     16
#define Cq     256
#define HWq    16384
#define INTERq 128
#define CHUNKS 128               // pixel chunks per sample (128 px each)

// scratch (no atomics anywhere)
__device__ float g_csum[Bq * CHUNKS * Cq];  // [b][chunk][c] partial channel sums (2 MB)
__device__ int   g_idx [Bq * 3];            // top-3 channels per sample

__device__ __forceinline__ float gelu_exact(float v) {
    return 0.5f * v * (1.0f + erff(v * 0.70710678118654752f));
}

// ---------------------------------------------------------------------------
// K1 (R4-exact, best known): single streaming pass over x.
//   Block = (b, 128-pixel chunk); 256 threads = 32 ch-groups x 8 px-slots.
//   Thread loads 8 channels x 4 float4; channel sums AND pixel dots in regs.
//   Writes out ch0 (GELU) + per-chunk channel partials. No hot-loop shuffles.
// ---------------------------------------------------------------------------
__global__ __launch_bounds__(256) void k1_stream(const float* __restrict__ x,
                                                 const float* __restrict__ W3,
                                                 float* __restrict__ out) {
    __shared__ float sw[Cq];
    __shared__ float scs[Cq][8];        // [channel][pw]   : 8 KB
    __shared__ float sdot[4][32][32];   // [seg][cw][pix%32]: 16 KB

    const int b     = blockIdx.x >> 7;
    const int chunk = blockIdx.x & 127;
    const int t  = threadIdx.x;
    const int cw = t >> 3;              // 0..31 channel group
    const int pw = t & 7;               // 0..7 pixel slot

    for (int i = t; i < Cq; i += 256) sw[i] = W3[i];
    __syncthreads();

    const float* xb = x + ((size_t)b * Cq + (size_t)cw * 8) * HWq
                        + (size_t)chunk * 128 + (size_t)pw * 4;

    float4 dot[4];
    #pragma unroll
    for (int s = 0; s < 4; ++s) dot[s] = make_float4(0.f, 0.f, 0.f, 0.f);
    float cs[8];
    #pragma unroll
    for (int j = 0; j < 8; ++j) cs[j] = 0.f;

    #pragma unroll
    for (int j = 0; j < 8; ++j) {
        const float w = sw[cw * 8 + j];
        const float* xc = xb + (size_t)j * HWq;
        #pragma unroll
        for (int s = 0; s < 4; ++s) {
            const float4 v = *reinterpret_cast<const float4*>(xc + s * 32);
            dot[s].x = fmaf(v.x, w, dot[s].x);
            dot[s].y = fmaf(v.y, w, dot[s].y);
            dot[s].z = fmaf(v.z, w, dot[s].z);
            dot[s].w = fmaf(v.w, w, dot[s].w);
            cs[j] += (v.x + v.y) + (v.z + v.w);
        }
    }

    #pragma unroll
    for (int j = 0; j < 8; ++j) scs[cw * 8 + j][pw] = cs[j];
    #pragma unroll
    for (int s = 0; s < 4; ++s)
        *reinterpret_cast<float4*>(&sdot[s][cw][pw * 4]) = dot[s];
    __syncthreads();

    {
        float s = 0.f;
        #pragma unroll
        for (int k = 0; k < 8; ++k) s += scs[t][k];
        g_csum[((size_t)b * CHUNKS + chunk) * Cq + t] = s;
    }

    if (t < 128) {
        const int s = t >> 5, q = t & 31;
        float d = 0.f;
        #pragma unroll
        for (int k = 0; k < 32; ++k) d += sdot[s][k][q];
        out[(size_t)b * 4 * HWq + (size_t)chunk * 128 + t] = gelu_exact(d);
    }
}

// ---------------------------------------------------------------------------
// KMID: the ENTIRE small pipeline in ONE block of 1024 threads, zero warp_sum:
//   phase0: pool p from g_csum (transposed smem sp_t[c][b])
//   phase1: g/theta/phi projections; thread = (column, batch) -> serial FMA
//   phase2: f = relu([th,ph].Wf + bf)  (warp 0, lanes 0..15)
//   phase3+4: wy = f*(g.Wz)+bz, BN over batch via shfl_xor in 16-lane groups,
//             residual +p, z -> sz (padded)
//   phase5: warp-per-batch top-3 shuffle-argmax (ties -> lowest index)
// ---------------------------------------------------------------------------
__global__ __launch_bounds__(1024) void kmid_pipeline(
    const float* __restrict__ Wg, const float* __restrict__ bg,
    const float* __restrict__ Wt, const float* __restrict__ bt,
    const float* __restrict__ Wp, const float* __restrict__ bp,
    const float* __restrict__ Wf, const float* __restrict__ bf,
    const float* __restrict__ Wz, const float* __restrict__ bz,
    const float* __restrict__ gamma, const float* __restrict__ beta)
{
    __shared__ float sp_t[Cq * 16];        // p transposed [c][b]        16 KB
    __shared__ float s_g [INTERq * 16];    // g_x [i][b]                  8 KB
    __shared__ float s_tp[2 * INTERq * 16 + 16]; // th|ph then reused as sz 16.1KB
    __shared__ float sf[16];

    const int t    = threadIdx.x;
    const int lane = t & 31;
    const int warp = t >> 5;
    const int bb   = t & 15;        // batch lane within 16-group
    const int colg = t >> 4;        // 0..63 column slot per round

    // ---- phase 0: pooled p ----
    #pragma unroll
    for (int j = 0; j < 4; ++j) {
        const int o = t + j * 1024;       // o = b*256 + c
        const int b = o >> 8, c = o & 255;
        const float* cs = g_csum + (size_t)b * CHUNKS * Cq + c;
        float s = 0.f;
        #pragma unroll 8
        for (int k = 0; k < CHUNKS; ++k) s += cs[(size_t)k * Cq];
        sp_t[c * 16 + b] = s * (1.0f / (float)HWq);
    }
    __syncthreads();

    // ---- phase 1: projections (6 rounds x 64 cols x 16 batches) ----
    #pragma unroll
    for (int r = 0; r < 6; ++r) {
        const int col = r * 64 + colg;       // 0..383
        const int cg  = col >> 7;            // 0:Wg 1:Wt 2:Wp (uniform per round)
        const int lc  = col & 127;
        const float* Wrow = (cg == 0) ? (Wg + (size_t)lc * Cq)
                          : (cg == 1) ? (Wt + (size_t)lc * Cq)
                                      : (Wp + (size_t)lc * Cq);
        float a0 = 0.f, a1 = 0.f, a2 = 0.f, a3 = 0.f;
        #pragma unroll 4
        for (int c = 0; c < Cq; c += 4) {
            a0 = fmaf(Wrow[c + 0], sp_t[(c + 0) * 16 + bb], a0);
            a1 = fmaf(Wrow[c + 1], sp_t[(c + 1) * 16 + bb], a1);
            a2 = fmaf(Wrow[c + 2], sp_t[(c + 2) * 16 + bb], a2);
            a3 = fmaf(Wrow[c + 3], sp_t[(c + 3) * 16 + bb], a3);
        }
        const float bias = (cg == 0) ? bg[lc] : (cg == 1) ? bt[lc] : bp[lc];
        const float v = ((a0 + a1) + (a2 + a3)) + bias;
        if (cg == 0)      s_g [lc * 16 + bb] = v;
        else if (cg == 1) s_tp[lc * 16 + bb] = v;                 // theta
        else              s_tp[(INTERq + lc) * 16 + bb] = v;      // phi
    }
    __syncthreads();

    // ---- phase 2: f[b] = relu([th,ph] . Wf + bf) ----
    if (warp == 0 && lane < 16) {
        float a0 = 0.f, a1 = 0.f;
        #pragma unroll 4
        for (int i = 0; i < 2 * INTERq; i += 2) {
            a0 = fmaf(s_tp[(i + 0) * 16 + lane], __ldg(Wf + i + 0), a0);
            a1 = fmaf(s_tp[(i + 1) * 16 + lane], __ldg(Wf + i + 1), a1);
        }
        sf[lane] = fmaxf(a0 + a1 + bf[0], 0.f);
    }
    __syncthreads();
    const float f = sf[bb];

    float* sz = s_tp;   // reuse as z [b][c] padded stride 257

    // ---- phase 3+4: wy, BN over batch, residual; 4 rounds x 64 cols ----
    #pragma unroll
    for (int r = 0; r < 4; ++r) {
        const int col = r * 64 + colg;       // 0..255
        const float* Wrow = Wz + (size_t)col * INTERq;
        float a0 = 0.f, a1 = 0.f, a2 = 0.f, a3 = 0.f;
        #pragma unroll 4
        for (int i = 0; i < INTERq; i += 4) {
            a0 = fmaf(Wrow[i + 0], s_g[(i + 0) * 16 + bb], a0);
            a1 = fmaf(Wrow[i + 1], s_g[(i + 1) * 16 + bb], a1);
            a2 = fmaf(Wrow[i + 2], s_g[(i + 2) * 16 + bb], a2);
            a3 = fmaf(Wrow[i + 3], s_g[(i + 3) * 16 + bb], a3);
        }
        const float wy = fmaf(f, ((a0 + a1) + (a2 + a3)), bz[col]);

        // BN stats across the 16-lane batch group
        float m = wy;
        m += __shfl_xor_sync(0xffffffffu, m, 1);
        m += __shfl_xor_sync(0xffffffffu, m, 2);
        m += __shfl_xor_sync(0xffffffffu, m, 4);
        m += __shfl_xor_sync(0xffffffffu, m, 8);
        m *= (1.0f / 16.0f);
        const float d = wy - m;
        float var = d * d;
        var += __shfl_xor_sync(0xffffffffu, var, 1);
        var += __shfl_xor_sync(0xffffffffu, var, 2);
        var += __shfl_xor_sync(0xffffffffu, var, 4);
        var += __shfl_xor_sync(0xffffffffu, var, 8);
        var *= (1.0f / 16.0f);
        const float inv = rsqrtf(var + 1e-5f);
        const float z = fmaf(gamma[col] * d, inv, beta[col]) + sp_t[col * 16 + bb];
        sz[bb * 257 + col] = z;   // written after all reads of s_tp (phase2 done)
    }
    __syncthreads();

    // ---- phase 5: top-3 per batch (sigmoid monotone -> topk on z) ----
    if (warp < 16) {
        float v[8];
        #pragma unroll
        for (int k = 0; k < 8; ++k) v[k] = sz[warp * 257 + k * 32 + lane];

        for (int j = 0; j < 3; ++j) {
            float bv = -INFINITY;
            int   bi = 0x7fffffff;
            #pragma unroll
            for (int k = 0; k < 8; ++k) {
                const int idx = k * 32 + lane;
                if (v[k] > bv) { bv = v[k]; bi = idx; }
            }
            #pragma unroll
            for (int off = 16; off > 0; off >>= 1) {
                const float ov = __shfl_down_sync(0xffffffffu, bv, off);
                const int   oi = __shfl_down_sync(0xffffffffu, bi, off);
                if (ov > bv || (ov == bv && oi < bi)) { bv = ov; bi = oi; }
            }
            bi = __shfl_sync(0xffffffffu, bi, 0);
            if (lane == 0) g_idx[warp * 3 + j] = bi;
            const int kk = bi >> 5;
            if ((bi & 31) == lane) {
                #pragma unroll
                for (int k = 0; k < 8; ++k) if (k == kk) v[k] = -INFINITY;
            }
        }
    }
}

// ---------------------------------------------------------------------------
// KEPI: gather top-3 channels into out ch1..3.
//   grid = 16*3 = 48 blocks x 1024 threads; 4 float4 per thread -> all 3 MB
//   in flight at once.
// ---------------------------------------------------------------------------
__global__ __launch_bounds__(1024) void kepi_gather(const float* __restrict__ x,
                                                    float* __restrict__ out) {
    const int b = blockIdx.x / 3, j = blockIdx.x % 3;
    const int ch = g_idx[b * 3 + j];
    const float* src = x + ((size_t)b * Cq + ch) * HWq;
    float* dst = out + ((size_t)b * 4 + 1 + j) * HWq;
    const int t = threadIdx.x;
    float4 v0 = *reinterpret_cast<const float4*>(src + t * 4);
    float4 v1 = *reinterpret_cast<const float4*>(src + 4096 + t * 4);
    float4 v2 = *reinterpret_cast<const float4*>(src + 8192 + t * 4);
    float4 v3 = *reinterpret_cast<const float4*>(src + 12288 + t * 4);
    *reinterpret_cast<float4*>(dst + t * 4)         = v0;
    *reinterpret_cast<float4*>(dst + 4096 + t * 4)  = v1;
    *reinterpret_cast<float4*>(dst + 8192 + t * 4)  = v2;
    *reinterpret_cast<float4*>(dst + 12288 + t * 4) = v3;
}

extern "C" void kernel_launch(void* const* d_in, const int* in_sizes, int n_in,
                              void* d_out, int out_size) {
    const float* x     = (const float*)d_in[0];
    const float* Wg    = (const float*)d_in[1];
    const float* bg    = (const float*)d_in[2];
    const float* Wt    = (const float*)d_in[3];
    const float* bt    = (const float*)d_in[4];
    const float* Wp    = (const float*)d_in[5];
    const float* bp    = (const float*)d_in[6];
    const float* Wf    = (const float*)d_in[7];
    const float* bf    = (const float*)d_in[8];
    const float* Wz    = (const float*)d_in[9];
    const float* bz    = (const float*)d_in[10];
    const float* gamma = (const float*)d_in[11];
    const float* beta  = (const float*)d_in[12];
    const float* W3    = (const float*)d_in[13];
    float* out = (float*)d_out;

    k1_stream<<<Bq * CHUNKS, 256>>>(x, W3, out);
    kmid_pipeline<<<1, 1024>>>(Wg, bg, Wt, bt, Wp, bp, Wf, bf, Wz, bz, gamma, beta);
    kepi_gather<<<Bq * 3, 1024>>>(x, out);
}

// round 11
// speedup vs baseline: 1.8487x; 1.8487x over previous
#include <cuda_runtime.h>
#include <cstdint>
#include <math.h>

#define Bq     16
#define Cq     256
#define HWq    16384
#define INTERq 128
#define CHUNKS 128               // pixel chunks per sample (128 px each)

// scratch (no cross-block atomics on data; flags only)
__device__ float g_csum[Bq * CHUNKS * Cq];  // [b][chunk][c] partial channel sums (2 MB)
__device__ float g_p   [Bq * Cq];           // pooled means
__device__ float g_wy  [Bq * Cq];           // pre-BN activations
__device__ int   g_idx [Bq * 3];            // top-3 channels per sample
__device__ int   g_done;                    // worker-completion counter
__device__ int   g_flag;                    // topk-ready flag

__device__ __forceinline__ float gelu_exact(float v) {
    return 0.5f * v * (1.0f + erff(v * 0.70710678118654752f));
}

__device__ __forceinline__ float warp_sum(float s) {
    s += __shfl_down_sync(0xffffffffu, s, 16);
    s += __shfl_down_sync(0xffffffffu, s, 8);
    s += __shfl_down_sync(0xffffffffu, s, 4);
    s += __shfl_down_sync(0xffffffffu, s, 2);
    s += __shfl_down_sync(0xffffffffu, s, 1);
    return s;
}

#define BAR(id, cnt) asm volatile("bar.sync %0, %1;" :: "r"(id), "r"(cnt) : "memory")

// ---------------------------------------------------------------------------
// K1 (R4-exact, proven 45.6us @ 75.8% DRAM): single streaming pass over x.
//   Block = (b, 128-pixel chunk); 256 threads = 32 ch-groups x 8 px-slots.
//   Also resets the ksmall flags (block 0) — stream-ordered vs ksmall.
// ---------------------------------------------------------------------------
__global__ __launch_bounds__(256) void k1_stream(const float* __restrict__ x,
                                                 const float* __restrict__ W3,
                                                 float* __restrict__ out) {
    __shared__ float sw[Cq];
    __shared__ float scs[Cq][8];        // [channel][pw]   : 8 KB
    __shared__ float sdot[4][32][32];   // [seg][cw][pix%32]: 16 KB

    if (blockIdx.x == 0 && threadIdx.x == 0) { g_done = 0; g_flag = 0; }

    const int b     = blockIdx.x >> 7;
    const int chunk = blockIdx.x & 127;
    const int t  = threadIdx.x;
    const int cw = t >> 3;              // 0..31 channel group
    const int pw = t & 7;               // 0..7 pixel slot

    for (int i = t; i < Cq; i += 256) sw[i] = W3[i];
    __syncthreads();

    const float* xb = x + ((size_t)b * Cq + (size_t)cw * 8) * HWq
                        + (size_t)chunk * 128 + (size_t)pw * 4;

    float4 dot[4];
    #pragma unroll
    for (int s = 0; s < 4; ++s) dot[s] = make_float4(0.f, 0.f, 0.f, 0.f);
    float cs[8];
    #pragma unroll
    for (int j = 0; j < 8; ++j) cs[j] = 0.f;

    #pragma unroll
    for (int j = 0; j < 8; ++j) {
        const float w = sw[cw * 8 + j];
        const float* xc = xb + (size_t)j * HWq;
        #pragma unroll
        for (int s = 0; s < 4; ++s) {
            const float4 v = *reinterpret_cast<const float4*>(xc + s * 32);
            dot[s].x = fmaf(v.x, w, dot[s].x);
            dot[s].y = fmaf(v.y, w, dot[s].y);
            dot[s].z = fmaf(v.z, w, dot[s].z);
            dot[s].w = fmaf(v.w, w, dot[s].w);
            cs[j] += (v.x + v.y) + (v.z + v.w);
        }
    }

    #pragma unroll
    for (int j = 0; j < 8; ++j) scs[cw * 8 + j][pw] = cs[j];
    #pragma unroll
    for (int s = 0; s < 4; ++s)
        *reinterpret_cast<float4*>(&sdot[s][cw][pw * 4]) = dot[s];
    __syncthreads();

    {
        float s = 0.f;
        #pragma unroll
        for (int k = 0; k < 8; ++k) s += scs[t][k];
        g_csum[((size_t)b * CHUNKS + chunk) * Cq + t] = s;
    }

    if (t < 128) {
        const int s = t >> 5, q = t & 31;
        float d = 0.f;
        #pragma unroll
        for (int k = 0; k < 32; ++k) d += sdot[s][k][q];
        out[(size_t)b * 4 * HWq + (size_t)chunk * 128 + t] = gelu_exact(d);
    }
}

// ---------------------------------------------------------------------------
// proj helper (R4-proven): warp handles 16 columns, coalesced weight reads.
// ---------------------------------------------------------------------------
__device__ __forceinline__ void proj_cols(const float* __restrict__ W,
                                          const float* __restrict__ bias,
                                          const float* sp, float* dst,
                                          int warp, int lane) {
    #pragma unroll 2
    for (int i = 0; i < 16; ++i) {
        const int col = warp * 16 + i;
        float a = 0.f;
        #pragma unroll
        for (int k = 0; k < 8; ++k) {
            const int idx = k * 32 + lane;
            a = fmaf(__ldg(W + col * Cq + idx), sp[idx], a);
        }
        a = warp_sum(a);
        if (lane == 0) dst[col] = a + bias[col];
    }
}

// ---------------------------------------------------------------------------
// KSMALL: entire post-K1 chain in ONE kernel. 48 blocks x 1024 threads.
//   blocks 0..15 (t<256): per-batch pool+proj+f+wy  (R4 k2 body, bar1/256)
//   last finisher block (t<512): BN over batch + top-3 (R4 k3 body, bar2/512)
//   all 48 blocks: spin on flag, then gather channel (b,j) = (bid/3, bid%3).
// ---------------------------------------------------------------------------
__global__ __launch_bounds__(1024) void ksmall(
    const float* __restrict__ x,
    const float* __restrict__ Wg, const float* __restrict__ bg,
    const float* __restrict__ Wt, const float* __restrict__ bt,
    const float* __restrict__ Wp, const float* __restrict__ bp,
    const float* __restrict__ Wf, const float* __restrict__ bf,
    const float* __restrict__ Wz, const float* __restrict__ bz,
    const float* __restrict__ gamma, const float* __restrict__ beta,
    float* __restrict__ out)
{
    __shared__ float sp[Cq];
    __shared__ float s_g[INTERq], s_th[INTERq], s_ph[INTERq];
    __shared__ float sf_sh;
    __shared__ float sz[Bq * Cq];       // 16 KB (k3 phase, last block only)
    __shared__ int   s_last;

    const int bid  = blockIdx.x;
    const int t    = threadIdx.x;
    const int lane = t & 31;
    const int warp = t >> 5;

    if (t == 0) s_last = 0;

    // ---------------- phase A: per-batch worker (blocks 0..15) ----------------
    if (bid < Bq) {
        if (t < 256) {
            const int b = bid;
            {
                const float* cs = g_csum + (size_t)b * CHUNKS * Cq + t;
                float s = 0.f;
                #pragma unroll 8
                for (int k = 0; k < CHUNKS; ++k) s += cs[(size_t)k * Cq];
                const float p = s * (1.0f / (float)HWq);
                sp[t] = p;
                g_p[b * Cq + t] = p;
            }
            BAR(1, 256);

            proj_cols(Wg, bg, sp, s_g,  warp, lane);
            proj_cols(Wt, bt, sp, s_th, warp, lane);
            proj_cols(Wp, bp, sp, s_ph, warp, lane);
            BAR(1, 256);

            if (warp == 0) {
                float a = 0.f;
                #pragma unroll
                for (int k = 0; k < 8; ++k) {
                    const int i = k * 32 + lane;
                    const float v = (i < INTERq) ? s_th[i] : s_ph[i - INTERq];
                    a = fmaf(v, __ldg(Wf + i), a);
                }
                a = warp_sum(a);
                if (lane == 0) sf_sh = fmaxf(a + bf[0], 0.f);
            }
            BAR(1, 256);
            const float f = sf_sh;

            #pragma unroll 2
            for (int i = 0; i < 32; ++i) {
                const int col = warp * 32 + i;
                float a = 0.f;
                #pragma unroll
                for (int k = 0; k < 4; ++k) {
                    const int idx = k * 32 + lane;
                    a = fmaf(__ldg(Wz + col * INTERq + idx), s_g[idx], a);
                }
                a = warp_sum(a);
                if (lane == 0) g_wy[b * Cq + col] = fmaf(f, a, bz[col]);
            }
        }
        __syncthreads();
        if (t == 0) {
            __threadfence();
            const int old = atomicAdd(&g_done, 1);
            if (old == Bq - 1) s_last = 1;
        }
    }
    __syncthreads();

    // ---------------- phase B: BN + top-3 (last finisher block only) ----------
    if (s_last) {
        if (t == 0) __threadfence();    // acquire other workers' g_wy/g_p
        __syncthreads();
        if (t < 512) {
            if (t < Cq) {
                const int c = t;
                float vals[Bq];
                #pragma unroll
                for (int b = 0; b < Bq; ++b) vals[b] = g_wy[b * Cq + c];
                float m = 0.f;
                #pragma unroll
                for (int b = 0; b < Bq; ++b) m += vals[b];
                m *= (1.0f / (float)Bq);
                float var = 0.f;
                #pragma unroll
                for (int b = 0; b < Bq; ++b) { const float d = vals[b] - m; var = fmaf(d, d, var); }
                var *= (1.0f / (float)Bq);
                const float inv = rsqrtf(var + 1e-5f);
                const float ga = gamma[c], be = beta[c];
                #pragma unroll
                for (int b = 0; b < Bq; ++b)
                    sz[b * Cq + c] = fmaf(ga * (vals[b] - m), inv, be) + g_p[b * Cq + c];
            }
            BAR(2, 512);

            // warp-per-sample top-3 (ties -> lowest index; sigmoid monotone)
            {
                float v[8];
                const int base = warp * Cq;
                #pragma unroll
                for (int k = 0; k < 8; ++k) v[k] = sz[base + k * 32 + lane];

                for (int j = 0; j < 3; ++j) {
                    float bv = -INFINITY;
                    int   bi = 0x7fffffff;
                    #pragma unroll
                    for (int k = 0; k < 8; ++k) {
                        const int idx = k * 32 + lane;
                        if (v[k] > bv) { bv = v[k]; bi = idx; }
                    }
                    #pragma unroll
                    for (int off = 16; off > 0; off >>= 1) {
                        const float ov = __shfl_down_sync(0xffffffffu, bv, off);
                        const int   oi = __shfl_down_sync(0xffffffffu, bi, off);
                        if (ov > bv || (ov == bv && oi < bi)) { bv = ov; bi = oi; }
                    }
                    bi = __shfl_sync(0xffffffffu, bi, 0);
                    if (lane == 0) g_idx[warp * 3 + j] = bi;
                    const int kk = bi >> 5;
                    if ((bi & 31) == lane) {
                        #pragma unroll
                        for (int k = 0; k < 8; ++k) if (k == kk) v[k] = -INFINITY;
                    }
                }
            }
        }
        __syncthreads();
        if (t == 0) { __threadfence(); atomicExch(&g_flag, 1); }
    }

    // ---------------- phase C: all 48 blocks gather ----------------------------
    if (t == 0) {
        while (atomicAdd(&g_flag, 0) == 0) { __nanosleep(64); }
        __threadfence();
    }
    __syncthreads();

    const int b = bid / 3, j = bid % 3;
    const int ch = g_idx[b * 3 + j];
    const float* src = x + ((size_t)b * Cq + ch) * HWq;
    float* dst = out + ((size_t)b * 4 + 1 + j) * HWq;
    const float4 v0 = *reinterpret_cast<const float4*>(src + t * 4);
    const float4 v1 = *reinterpret_cast<const float4*>(src + 4096 + t * 4);
    const float4 v2 = *reinterpret_cast<const float4*>(src + 8192 + t * 4);
    const float4 v3 = *reinterpret_cast<const float4*>(src + 12288 + t * 4);
    *reinterpret_cast<float4*>(dst + t * 4)         = v0;
    *reinterpret_cast<float4*>(dst + 4096 + t * 4)  = v1;
    *reinterpret_cast<float4*>(dst + 8192 + t * 4)  = v2;
    *reinterpret_cast<float4*>(dst + 12288 + t * 4) = v3;
}

extern "C" void kernel_launch(void* const* d_in, const int* in_sizes, int n_in,
                              void* d_out, int out_size) {
    const float* x     = (const float*)d_in[0];
    const float* Wg    = (const float*)d_in[1];
    const float* bg    = (const float*)d_in[2];
    const float* Wt    = (const float*)d_in[3];
    const float* bt    = (const float*)d_in[4];
    const float* Wp    = (const float*)d_in[5];
    const float* bp    = (const float*)d_in[6];
    const float* Wf    = (const float*)d_in[7];
    const float* bf    = (const float*)d_in[8];
    const float* Wz    = (const float*)d_in[9];
    const float* bz    = (const float*)d_in[10];
    const float* gamma = (const float*)d_in[11];
    const float* beta  = (const float*)d_in[12];
    const float* W3    = (const float*)d_in[13];
    float* out = (float*)d_out;

    k1_stream<<<Bq * CHUNKS, 256>>>(x, W3, out);
    ksmall<<<Bq * 3, 1024>>>(x, Wg, bg, Wt, bt, Wp, bp, Wf, bf,
                             Wz, bz, gamma, beta, out);
}

// round 12
// speedup vs baseline: 2.6898x; 1.4550x over previous
#include <cuda_runtime.h>
#include <cstdint>
#include <math.h>

#define Bq     16
#define Cq     256
#define HWq    16384
#define INTERq 128
#define CHUNKS 128               // pixel chunks per sample (128 px each)

// scratch (no atomics anywhere)
__device__ float g_csum[Bq * CHUNKS * Cq];  // [b][chunk][c] partial channel sums (2 MB)
__device__ float g_pt  [Cq * Bq];           // pooled means TRANSPOSED [c][b]
__device__ float g_gtp [384 * Bq];          // proj outputs [col][b]: g|theta|phi
__device__ float g_wyt [Cq * Bq];           // pre-BN activations [c][b]
__device__ int   g_idx [Bq * 3];            // top-3 channels per sample

__device__ __forceinline__ float gelu_exact(float v) {
    return 0.5f * v * (1.0f + erff(v * 0.70710678118654752f));
}

// ---------------------------------------------------------------------------
// K1 (R4-exact, proven 45.6us @ 75.8% DRAM): single streaming pass over x.
// ---------------------------------------------------------------------------
__global__ __launch_bounds__(256) void k1_stream(const float* __restrict__ x,
                                                 const float* __restrict__ W3,
                                                 float* __restrict__ out) {
    __shared__ float sw[Cq];
    __shared__ float scs[Cq][8];        // [channel][pw]   : 8 KB
    __shared__ float sdot[4][32][32];   // [seg][cw][pix%32]: 16 KB

    const int b     = blockIdx.x >> 7;
    const int chunk = blockIdx.x & 127;
    const int t  = threadIdx.x;
    const int cw = t >> 3;              // 0..31 channel group
    const int pw = t & 7;               // 0..7 pixel slot

    for (int i = t; i < Cq; i += 256) sw[i] = W3[i];
    __syncthreads();

    const float* xb = x + ((size_t)b * Cq + (size_t)cw * 8) * HWq
                        + (size_t)chunk * 128 + (size_t)pw * 4;

    float4 dot[4];
    #pragma unroll
    for (int s = 0; s < 4; ++s) dot[s] = make_float4(0.f, 0.f, 0.f, 0.f);
    float cs[8];
    #pragma unroll
    for (int j = 0; j < 8; ++j) cs[j] = 0.f;

    #pragma unroll
    for (int j = 0; j < 8; ++j) {
        const float w = sw[cw * 8 + j];
        const float* xc = xb + (size_t)j * HWq;
        #pragma unroll
        for (int s = 0; s < 4; ++s) {
            const float4 v = *reinterpret_cast<const float4*>(xc + s * 32);
            dot[s].x = fmaf(v.x, w, dot[s].x);
            dot[s].y = fmaf(v.y, w, dot[s].y);
            dot[s].z = fmaf(v.z, w, dot[s].z);
            dot[s].w = fmaf(v.w, w, dot[s].w);
            cs[j] += (v.x + v.y) + (v.z + v.w);
        }
    }

    #pragma unroll
    for (int j = 0; j < 8; ++j) scs[cw * 8 + j][pw] = cs[j];
    #pragma unroll
    for (int s = 0; s < 4; ++s)
        *reinterpret_cast<float4*>(&sdot[s][cw][pw * 4]) = dot[s];
    __syncthreads();

    {
        float s = 0.f;
        #pragma unroll
        for (int k = 0; k < 8; ++k) s += scs[t][k];
        g_csum[((size_t)b * CHUNKS + chunk) * Cq + t] = s;
    }

    if (t < 128) {
        const int s = t >> 5, q = t & 31;
        float d = 0.f;
        #pragma unroll
        for (int k = 0; k < 32; ++k) d += sdot[s][k][q];
        out[(size_t)b * 4 * HWq + (size_t)chunk * 128 + t] = gelu_exact(d);
    }
}

// ---------------------------------------------------------------------------
// KPOOL: 16 blocks (one per b) x 1024 threads. t = qq*256 + c; each thread
//   sums 32 coalesced chunk rows; 4-way smem combine; write p transposed.
// ---------------------------------------------------------------------------
__global__ __launch_bounds__(1024) void kpool() {
    __shared__ float part[4][Cq];
    const int b  = blockIdx.x;
    const int t  = threadIdx.x;
    const int c  = t & 255;
    const int qq = t >> 8;

    const float* cs = g_csum + (size_t)b * CHUNKS * Cq + (size_t)qq * 32 * Cq + c;
    float s = 0.f;
    #pragma unroll 8
    for (int k = 0; k < 32; ++k) s += cs[(size_t)k * Cq];
    part[qq][c] = s;
    __syncthreads();
    if (t < Cq)
        g_pt[t * Bq + b] = ((part[0][t] + part[1][t]) + (part[2][t] + part[3][t]))
                         * (1.0f / (float)HWq);
}

// ---------------------------------------------------------------------------
// KPROJ: 48 blocks x 128 threads; block handles 8 of 384 columns
//   (cols 0..127 -> Wg/g, 128..255 -> Wt/theta, 256..383 -> Wp/phi).
//   Batch-in-lane: lane = (slot-high, batch-low); serial register FMA dots
//   from smem only. Zero warp reductions, zero LDG in the dot loop.
// ---------------------------------------------------------------------------
__global__ __launch_bounds__(128) void kproj(
    const float* __restrict__ Wg, const float* __restrict__ bg,
    const float* __restrict__ Wt, const float* __restrict__ bt,
    const float* __restrict__ Wp, const float* __restrict__ bp)
{
    __shared__ float sp_t[Cq * Bq];   // 16 KB, [i][b]
    __shared__ float swt[8][Cq];      // 8 KB
    __shared__ float sb[8];

    const int t    = threadIdx.x;
    const int col0 = blockIdx.x * 8;

    #pragma unroll
    for (int i = 0; i < 32; ++i) sp_t[t + i * 128] = g_pt[t + i * 128];

    #pragma unroll
    for (int r = 0; r < 8; ++r) {
        const int col = col0 + r;
        const int cg  = col >> 7;
        const int lc  = col & 127;
        const float* Wrow = (cg == 0) ? (Wg + (size_t)lc * Cq)
                          : (cg == 1) ? (Wt + (size_t)lc * Cq)
                                      : (Wp + (size_t)lc * Cq);
        swt[r][t] = Wrow[t];
        swt[r][t + 128] = Wrow[t + 128];
        if (t == r) sb[r] = (cg == 0) ? bg[lc] : (cg == 1) ? bt[lc] : bp[lc];
    }
    __syncthreads();

    const int b    = t & 15;          // batch
    const int slot = t >> 4;          // 0..7 column slot
    float a0 = 0.f, a1 = 0.f, a2 = 0.f, a3 = 0.f;
    #pragma unroll 8
    for (int i = 0; i < Cq; i += 4) {
        a0 = fmaf(swt[slot][i + 0], sp_t[(i + 0) * Bq + b], a0);
        a1 = fmaf(swt[slot][i + 1], sp_t[(i + 1) * Bq + b], a1);
        a2 = fmaf(swt[slot][i + 2], sp_t[(i + 2) * Bq + b], a2);
        a3 = fmaf(swt[slot][i + 3], sp_t[(i + 3) * Bq + b], a3);
    }
    g_gtp[(col0 + slot) * Bq + b] = ((a0 + a1) + (a2 + a3)) + sb[slot];
}

// ---------------------------------------------------------------------------
// KWY: 32 blocks x 128 threads; block handles 8 of 256 Wz columns.
//   warp 0 lanes 0..15 compute f[b] = relu([th,ph].Wf + bf) in parallel with
//   other warps' staging; dots from smem; wy = f*dot + bz -> g_wyt.
// ---------------------------------------------------------------------------
__global__ __launch_bounds__(128) void kwy(
    const float* __restrict__ Wf, const float* __restrict__ bf,
    const float* __restrict__ Wz, const float* __restrict__ bz)
{
    __shared__ float sg_t[INTERq * Bq];   // 8 KB [i][b]
    __shared__ float stp [2 * INTERq * Bq]; // 16 KB [i][b] (th|ph)
    __shared__ float swz[8][INTERq];      // 4 KB
    __shared__ float swf[2 * INTERq];     // 1 KB
    __shared__ float sf[Bq];
    __shared__ float sbz[8];

    const int t    = threadIdx.x;
    const int col0 = blockIdx.x * 8;

    #pragma unroll
    for (int i = 0; i < 16; ++i) sg_t[t + i * 128] = g_gtp[t + i * 128];
    #pragma unroll
    for (int i = 0; i < 32; ++i) stp[t + i * 128] = g_gtp[2048 + t + i * 128];
    swf[t] = Wf[t]; swf[t + 128] = Wf[t + 128];
    #pragma unroll
    for (int r = 0; r < 8; ++r) swz[r][t] = Wz[(size_t)(col0 + r) * INTERq + t];
    if (t < 8) sbz[t] = bz[col0 + t];
    __syncthreads();

    // f (warp 0, lanes 0..15)
    if (t < 16) {
        float a0 = 0.f, a1 = 0.f;
        #pragma unroll 8
        for (int i = 0; i < 2 * INTERq; i += 2) {
            a0 = fmaf(stp[(i + 0) * Bq + t], swf[i + 0], a0);
            a1 = fmaf(stp[(i + 1) * Bq + t], swf[i + 1], a1);
        }
        sf[t] = fmaxf(a0 + a1 + bf[0], 0.f);
    }

    const int b    = t & 15;
    const int slot = t >> 4;
    float a0 = 0.f, a1 = 0.f, a2 = 0.f, a3 = 0.f;
    #pragma unroll 8
    for (int i = 0; i < INTERq; i += 4) {
        a0 = fmaf(swz[slot][i + 0], sg_t[(i + 0) * Bq + b], a0);
        a1 = fmaf(swz[slot][i + 1], sg_t[(i + 1) * Bq + b], a1);
        a2 = fmaf(swz[slot][i + 2], sg_t[(i + 2) * Bq + b], a2);
        a3 = fmaf(swz[slot][i + 3], sg_t[(i + 3) * Bq + b], a3);
    }
    __syncthreads();
    g_wyt[(col0 + slot) * Bq + b] = fmaf(sf[b], ((a0 + a1) + (a2 + a3)), sbz[slot]);
}

// ---------------------------------------------------------------------------
// KBN: 1 block x 512. BN over batch (coalesced transposed reads) + residual,
//   then warp-per-sample top-3 shuffle-argmax (ties -> lowest index).
// ---------------------------------------------------------------------------
__global__ __launch_bounds__(512) void kbn_topk(const float* __restrict__ gamma,
                                                const float* __restrict__ beta) {
    __shared__ float sz[Bq * Cq];
    const int t = threadIdx.x;

    if (t < Cq) {
        const int c = t;
        float vals[Bq];
        const float4* w4 = reinterpret_cast<const float4*>(g_wyt + c * Bq);
        const float4* p4 = reinterpret_cast<const float4*>(g_pt  + c * Bq);
        #pragma unroll
        for (int k = 0; k < 4; ++k) {
            const float4 v = w4[k];
            vals[k * 4 + 0] = v.x; vals[k * 4 + 1] = v.y;
            vals[k * 4 + 2] = v.z; vals[k * 4 + 3] = v.w;
        }
        float m = 0.f;
        #pragma unroll
        for (int b = 0; b < Bq; ++b) m += vals[b];
        m *= (1.0f / (float)Bq);
        float var = 0.f;
        #pragma unroll
        for (int b = 0; b < Bq; ++b) { const float d = vals[b] - m; var = fmaf(d, d, var); }
        var *= (1.0f / (float)Bq);
        const float inv = rsqrtf(var + 1e-5f);
        const float ga = gamma[c], be = beta[c];
        #pragma unroll
        for (int k = 0; k < 4; ++k) {
            const float4 p = p4[k];
            sz[(k * 4 + 0) * Cq + c] = fmaf(ga * (vals[k * 4 + 0] - m), inv, be) + p.x;
            sz[(k * 4 + 1) * Cq + c] = fmaf(ga * (vals[k * 4 + 1] - m), inv, be) + p.y;
            sz[(k * 4 + 2) * Cq + c] = fmaf(ga * (vals[k * 4 + 2] - m), inv, be) + p.z;
            sz[(k * 4 + 3) * Cq + c] = fmaf(ga * (vals[k * 4 + 3] - m), inv, be) + p.w;
        }
    }
    __syncthreads();

    const int warp = t >> 5;   // 16 warps = 16 samples
    const int lane = t & 31;
    {
        float v[8];
        const int base = warp * Cq;
        #pragma unroll
        for (int k = 0; k < 8; ++k) v[k] = sz[base + k * 32 + lane];

        for (int j = 0; j < 3; ++j) {
            float bv = -INFINITY;
            int   bi = 0x7fffffff;
            #pragma unroll
            for (int k = 0; k < 8; ++k) {
                const int idx = k * 32 + lane;
                if (v[k] > bv) { bv = v[k]; bi = idx; }
            }
            #pragma unroll
            for (int off = 16; off > 0; off >>= 1) {
                const float ov = __shfl_down_sync(0xffffffffu, bv, off);
                const int   oi = __shfl_down_sync(0xffffffffu, bi, off);
                if (ov > bv || (ov == bv && oi < bi)) { bv = ov; bi = oi; }
            }
            bi = __shfl_sync(0xffffffffu, bi, 0);
            if (lane == 0) g_idx[warp * 3 + j] = bi;
            const int kk = bi >> 5;
            if ((bi & 31) == lane) {
                #pragma unroll
                for (int k = 0; k < 8; ++k) if (k == kk) v[k] = -INFINITY;
            }
        }
    }
}

// ---------------------------------------------------------------------------
// KGATHER (R10-proven): 48 blocks x 1024; 4 float4 per thread.
// ---------------------------------------------------------------------------
__global__ __launch_bounds__(1024) void kgather(const float* __restrict__ x,
                                                float* __restrict__ out) {
    const int b = blockIdx.x / 3, j = blockIdx.x % 3;
    const int ch = g_idx[b * 3 + j];
    const float* src = x + ((size_t)b * Cq + ch) * HWq;
    float* dst = out + ((size_t)b * 4 + 1 + j) * HWq;
    const int t = threadIdx.x;
    const float4 v0 = *reinterpret_cast<const float4*>(src + t * 4);
    const float4 v1 = *reinterpret_cast<const float4*>(src + 4096 + t * 4);
    const float4 v2 = *reinterpret_cast<const float4*>(src + 8192 + t * 4);
    const float4 v3 = *reinterpret_cast<const float4*>(src + 12288 + t * 4);
    *reinterpret_cast<float4*>(dst + t * 4)         = v0;
    *reinterpret_cast<float4*>(dst + 4096 + t * 4)  = v1;
    *reinterpret_cast<float4*>(dst + 8192 + t * 4)  = v2;
    *reinterpret_cast<float4*>(dst + 12288 + t * 4) = v3;
}

extern "C" void kernel_launch(void* const* d_in, const int* in_sizes, int n_in,
                              void* d_out, int out_size) {
    const float* x     = (const float*)d_in[0];
    const float* Wg    = (const float*)d_in[1];
    const float* bg    = (const float*)d_in[2];
    const float* Wt    = (const float*)d_in[3];
    const float* bt    = (const float*)d_in[4];
    const float* Wp    = (const float*)d_in[5];
    const float* bp    = (const float*)d_in[6];
    const float* Wf    = (const float*)d_in[7];
    const float* bf    = (const float*)d_in[8];
    const float* Wz    = (const float*)d_in[9];
    const float* bz    = (const float*)d_in[10];
    const float* gamma = (const float*)d_in[11];
    const float* beta  = (const float*)d_in[12];
    const float* W3    = (const float*)d_in[13];
    float* out = (float*)d_out;

    k1_stream<<<Bq * CHUNKS, 256>>>(x, W3, out);
    kpool<<<Bq, 1024>>>();
    kproj<<<48, 128>>>(Wg, bg, Wt, bt, Wp, bp);
    kwy<<<32, 128>>>(Wf, bf, Wz, bz);
    kbn_topk<<<1, 512>>>(gamma, beta);
    kgather<<<Bq * 3, 1024>>>(x, out);
}

// round 13
// speedup vs baseline: 2.7549x; 1.0242x over previous
#include <cuda_runtime.h>
#include <cstdint>
#include <math.h>

#define Bq     16
#define Cq     256
#define HWq    16384
#define INTERq 128
#define CHUNKS 128               // pixel chunks per sample (128 px each)

// scratch (no atomics anywhere)
__device__ float g_csum[Bq * CHUNKS * Cq];  // [b][chunk][c] partial channel sums (2 MB)
__device__ float g_pt  [Cq * Bq];           // pooled means TRANSPOSED [c][b]
__device__ float g_gtp [384 * Bq];          // proj outputs [col][b]: g|theta|phi
__device__ float g_wyt [Cq * Bq];           // pre-BN activations [c][b]
__device__ int   g_idx [Bq * 3];            // top-3 channels per sample

__device__ __forceinline__ float gelu_exact(float v) {
    return 0.5f * v * (1.0f + erff(v * 0.70710678118654752f));
}

// ---------------------------------------------------------------------------
// K1 (R4-exact, proven 45.6us @ 75.8% DRAM): single streaming pass over x.
// ---------------------------------------------------------------------------
__global__ __launch_bounds__(256) void k1_stream(const float* __restrict__ x,
                                                 const float* __restrict__ W3,
                                                 float* __restrict__ out) {
    __shared__ float sw[Cq];
    __shared__ float scs[Cq][8];        // [channel][pw]   : 8 KB
    __shared__ float sdot[4][32][32];   // [seg][cw][pix%32]: 16 KB

    const int b     = blockIdx.x >> 7;
    const int chunk = blockIdx.x & 127;
    const int t  = threadIdx.x;
    const int cw = t >> 3;              // 0..31 channel group
    const int pw = t & 7;               // 0..7 pixel slot

    for (int i = t; i < Cq; i += 256) sw[i] = W3[i];
    __syncthreads();

    const float* xb = x + ((size_t)b * Cq + (size_t)cw * 8) * HWq
                        + (size_t)chunk * 128 + (size_t)pw * 4;

    float4 dot[4];
    #pragma unroll
    for (int s = 0; s < 4; ++s) dot[s] = make_float4(0.f, 0.f, 0.f, 0.f);
    float cs[8];
    #pragma unroll
    for (int j = 0; j < 8; ++j) cs[j] = 0.f;

    #pragma unroll
    for (int j = 0; j < 8; ++j) {
        const float w = sw[cw * 8 + j];
        const float* xc = xb + (size_t)j * HWq;
        #pragma unroll
        for (int s = 0; s < 4; ++s) {
            const float4 v = *reinterpret_cast<const float4*>(xc + s * 32);
            dot[s].x = fmaf(v.x, w, dot[s].x);
            dot[s].y = fmaf(v.y, w, dot[s].y);
            dot[s].z = fmaf(v.z, w, dot[s].z);
            dot[s].w = fmaf(v.w, w, dot[s].w);
            cs[j] += (v.x + v.y) + (v.z + v.w);
        }
    }

    #pragma unroll
    for (int j = 0; j < 8; ++j) scs[cw * 8 + j][pw] = cs[j];
    #pragma unroll
    for (int s = 0; s < 4; ++s)
        *reinterpret_cast<float4*>(&sdot[s][cw][pw * 4]) = dot[s];
    __syncthreads();

    {
        float s = 0.f;
        #pragma unroll
        for (int k = 0; k < 8; ++k) s += scs[t][k];
        g_csum[((size_t)b * CHUNKS + chunk) * Cq + t] = s;
    }

    if (t < 128) {
        const int s = t >> 5, q = t & 31;
        float d = 0.f;
        #pragma unroll
        for (int k = 0; k < 32; ++k) d += sdot[s][k][q];
        out[(size_t)b * 4 * HWq + (size_t)chunk * 128 + t] = gelu_exact(d);
    }
}

// ---------------------------------------------------------------------------
// KPOOL: 16 blocks (one per b) x 1024 threads (R12-proven).
// ---------------------------------------------------------------------------
__global__ __launch_bounds__(1024) void kpool() {
    __shared__ float part[4][Cq];
    const int b  = blockIdx.x;
    const int t  = threadIdx.x;
    const int c  = t & 255;
    const int qq = t >> 8;

    const float* cs = g_csum + (size_t)b * CHUNKS * Cq + (size_t)qq * 32 * Cq + c;
    float s = 0.f;
    #pragma unroll 8
    for (int k = 0; k < 32; ++k) s += cs[(size_t)k * Cq];
    part[qq][c] = s;
    __syncthreads();
    if (t < Cq)
        g_pt[t * Bq + b] = ((part[0][t] + part[1][t]) + (part[2][t] + part[3][t]))
                         * (1.0f / (float)HWq);
}

// ---------------------------------------------------------------------------
// KPROJ: 24 blocks x 256 threads; block = 16 of 384 columns. float4 staging.
//   Batch-in-lane serial FMA dots from smem only; zero reductions.
// ---------------------------------------------------------------------------
__global__ __launch_bounds__(256) void kproj(
    const float* __restrict__ Wg, const float* __restrict__ bg,
    const float* __restrict__ Wt, const float* __restrict__ bt,
    const float* __restrict__ Wp, const float* __restrict__ bp)
{
    __shared__ float sp_t[Cq * Bq];    // 16 KB [i][b]
    __shared__ float swt[16][Cq];      // 16 KB
    __shared__ float sb[16];

    const int t    = threadIdx.x;
    const int col0 = blockIdx.x * 16;

    // stage p (4096 floats = 1024 float4, 4 iters)
    #pragma unroll
    for (int j = 0; j < 4; ++j)
        reinterpret_cast<float4*>(sp_t)[j * 256 + t] =
            reinterpret_cast<const float4*>(g_pt)[j * 256 + t];

    // stage 16 weight rows (4096 floats = 1024 float4, 4 iters; 4 rows/iter)
    #pragma unroll
    for (int j = 0; j < 4; ++j) {
        const int id = j * 256 + t;           // float4 id
        const int r  = id >> 6;               // row 0..15
        const int c4 = id & 63;
        const int col = col0 + r;
        const int cg  = col >> 7;
        const int lc  = col & 127;
        const float* Wrow = (cg == 0) ? (Wg + (size_t)lc * Cq)
                          : (cg == 1) ? (Wt + (size_t)lc * Cq)
                                      : (Wp + (size_t)lc * Cq);
        reinterpret_cast<float4*>(&swt[r][0])[c4] =
            reinterpret_cast<const float4*>(Wrow)[c4];
    }
    if (t < 16) {
        const int col = col0 + t;
        const int cg  = col >> 7;
        const int lc  = col & 127;
        sb[t] = (cg == 0) ? bg[lc] : (cg == 1) ? bt[lc] : bp[lc];
    }
    __syncthreads();

    const int b    = t & 15;          // batch
    const int slot = t >> 4;          // 0..15 column slot
    float a0 = 0.f, a1 = 0.f, a2 = 0.f, a3 = 0.f;
    #pragma unroll 8
    for (int i = 0; i < Cq; i += 4) {
        a0 = fmaf(swt[slot][i + 0], sp_t[(i + 0) * Bq + b], a0);
        a1 = fmaf(swt[slot][i + 1], sp_t[(i + 1) * Bq + b], a1);
        a2 = fmaf(swt[slot][i + 2], sp_t[(i + 2) * Bq + b], a2);
        a3 = fmaf(swt[slot][i + 3], sp_t[(i + 3) * Bq + b], a3);
    }
    g_gtp[(col0 + slot) * Bq + b] = ((a0 + a1) + (a2 + a3)) + sb[slot];
}

// ---------------------------------------------------------------------------
// KWY: 16 blocks x 256 threads; block = 16 of 256 Wz columns. float4 staging.
//   lanes 0..15 compute f[b]; then wy = f*dot + bz -> g_wyt.
// ---------------------------------------------------------------------------
__global__ __launch_bounds__(256) void kwy(
    const float* __restrict__ Wf, const float* __restrict__ bf,
    const float* __restrict__ Wz, const float* __restrict__ bz)
{
    __shared__ float sg_t[INTERq * Bq];      // 8 KB [i][b]
    __shared__ float stp [2 * INTERq * Bq];  // 16 KB [i][b] (th|ph)
    __shared__ float swz[16][INTERq];        // 8 KB
    __shared__ float swf[2 * INTERq];        // 1 KB
    __shared__ float sf[Bq];
    __shared__ float sbz[16];

    const int t    = threadIdx.x;
    const int col0 = blockIdx.x * 16;

    // stage g (2048 floats = 512 float4, 2 iters)
    #pragma unroll
    for (int j = 0; j < 2; ++j)
        reinterpret_cast<float4*>(sg_t)[j * 256 + t] =
            reinterpret_cast<const float4*>(g_gtp)[j * 256 + t];
    // stage th|ph (4096 floats = 1024 float4, 4 iters)
    #pragma unroll
    for (int j = 0; j < 4; ++j)
        reinterpret_cast<float4*>(stp)[j * 256 + t] =
            reinterpret_cast<const float4*>(g_gtp + 2048)[j * 256 + t];
    // stage Wz rows (16 x 128 = 2048 floats = 512 float4, 2 iters; 8 rows/iter)
    #pragma unroll
    for (int j = 0; j < 2; ++j) {
        const int id = j * 256 + t;          // float4 id
        const int r  = id >> 5;              // row 0..15
        const int c4 = id & 31;
        reinterpret_cast<float4*>(&swz[r][0])[c4] =
            reinterpret_cast<const float4*>(Wz + (size_t)(col0 + r) * INTERq)[c4];
    }
    swf[t] = Wf[t];
    if (t < 16) sbz[t] = bz[col0 + t];
    __syncthreads();

    // f (lanes 0..15)
    if (t < 16) {
        float a0 = 0.f, a1 = 0.f;
        #pragma unroll 8
        for (int i = 0; i < 2 * INTERq; i += 2) {
            a0 = fmaf(stp[(i + 0) * Bq + t], swf[i + 0], a0);
            a1 = fmaf(stp[(i + 1) * Bq + t], swf[i + 1], a1);
        }
        sf[t] = fmaxf(a0 + a1 + bf[0], 0.f);
    }

    const int b    = t & 15;
    const int slot = t >> 4;
    float a0 = 0.f, a1 = 0.f, a2 = 0.f, a3 = 0.f;
    #pragma unroll 8
    for (int i = 0; i < INTERq; i += 4) {
        a0 = fmaf(swz[slot][i + 0], sg_t[(i + 0) * Bq + b], a0);
        a1 = fmaf(swz[slot][i + 1], sg_t[(i + 1) * Bq + b], a1);
        a2 = fmaf(swz[slot][i + 2], sg_t[(i + 2) * Bq + b], a2);
        a3 = fmaf(swz[slot][i + 3], sg_t[(i + 3) * Bq + b], a3);
    }
    __syncthreads();
    g_wyt[(col0 + slot) * Bq + b] = fmaf(sf[b], ((a0 + a1) + (a2 + a3)), sbz[slot]);
}

// ---------------------------------------------------------------------------
// KBN (R12-proven): 1 block x 512. BN over batch + residual + top-3.
// ---------------------------------------------------------------------------
__global__ __launch_bounds__(512) void kbn_topk(const float* __restrict__ gamma,
                                                const float* __restrict__ beta) {
    __shared__ float sz[Bq * Cq];
    const int t = threadIdx.x;

    if (t < Cq) {
        const int c = t;
        float vals[Bq];
        const float4* w4 = reinterpret_cast<const float4*>(g_wyt + c * Bq);
        const float4* p4 = reinterpret_cast<const float4*>(g_pt  + c * Bq);
        #pragma unroll
        for (int k = 0; k < 4; ++k) {
            const float4 v = w4[k];
            vals[k * 4 + 0] = v.x; vals[k * 4 + 1] = v.y;
            vals[k * 4 + 2] = v.z; vals[k * 4 + 3] = v.w;
        }
        float m = 0.f;
        #pragma unroll
        for (int b = 0; b < Bq; ++b) m += vals[b];
        m *= (1.0f / (float)Bq);
        float var = 0.f;
        #pragma unroll
        for (int b = 0; b < Bq; ++b) { const float d = vals[b] - m; var = fmaf(d, d, var); }
        var *= (1.0f / (float)Bq);
        const float inv = rsqrtf(var + 1e-5f);
        const float ga = gamma[c], be = beta[c];
        #pragma unroll
        for (int k = 0; k < 4; ++k) {
            const float4 p = p4[k];
            sz[(k * 4 + 0) * Cq + c] = fmaf(ga * (vals[k * 4 + 0] - m), inv, be) + p.x;
            sz[(k * 4 + 1) * Cq + c] = fmaf(ga * (vals[k * 4 + 1] - m), inv, be) + p.y;
            sz[(k * 4 + 2) * Cq + c] = fmaf(ga * (vals[k * 4 + 2] - m), inv, be) + p.z;
            sz[(k * 4 + 3) * Cq + c] = fmaf(ga * (vals[k * 4 + 3] - m), inv, be) + p.w;
        }
    }
    __syncthreads();

    const int warp = t >> 5;   // 16 warps = 16 samples
    const int lane = t & 31;
    {
        float v[8];
        const int base = warp * Cq;
        #pragma unroll
        for (int k = 0; k < 8; ++k) v[k] = sz[base + k * 32 + lane];

        for (int j = 0; j < 3; ++j) {
            float bv = -INFINITY;
            int   bi = 0x7fffffff;
            #pragma unroll
            for (int k = 0; k < 8; ++k) {
                const int idx = k * 32 + lane;
                if (v[k] > bv) { bv = v[k]; bi = idx; }
            }
            #pragma unroll
            for (int off = 16; off > 0; off >>= 1) {
                const float ov = __shfl_down_sync(0xffffffffu, bv, off);
                const int   oi = __shfl_down_sync(0xffffffffu, bi, off);
                if (ov > bv || (ov == bv && oi < bi)) { bv = ov; bi = oi; }
            }
            bi = __shfl_sync(0xffffffffu, bi, 0);
            if (lane == 0) g_idx[warp * 3 + j] = bi;
            const int kk = bi >> 5;
            if ((bi & 31) == lane) {
                #pragma unroll
                for (int k = 0; k < 8; ++k) if (k == kk) v[k] = -INFINITY;
            }
        }
    }
}

// ---------------------------------------------------------------------------
// KGATHER (R10-proven): 48 blocks x 1024; 4 float4 per thread.
// ---------------------------------------------------------------------------
__global__ __launch_bounds__(1024) void kgather(const float* __restrict__ x,
                                                float* __restrict__ out) {
    const int b = blockIdx.x / 3, j = blockIdx.x % 3;
    const int ch = g_idx[b * 3 + j];
    const float* src = x + ((size_t)b * Cq + ch) * HWq;
    float* dst = out + ((size_t)b * 4 + 1 + j) * HWq;
    const int t = threadIdx.x;
    const float4 v0 = *reinterpret_cast<const float4*>(src + t * 4);
    const float4 v1 = *reinterpret_cast<const float4*>(src + 4096 + t * 4);
    const float4 v2 = *reinterpret_cast<const float4*>(src + 8192 + t * 4);
    const float4 v3 = *reinterpret_cast<const float4*>(src + 12288 + t * 4);
    *reinterpret_cast<float4*>(dst + t * 4)         = v0;
    *reinterpret_cast<float4*>(dst + 4096 + t * 4)  = v1;
    *reinterpret_cast<float4*>(dst + 8192 + t * 4)  = v2;
    *reinterpret_cast<float4*>(dst + 12288 + t * 4) = v3;
}

extern "C" void kernel_launch(void* const* d_in, const int* in_sizes, int n_in,
                              void* d_out, int out_size) {
    const float* x     = (const float*)d_in[0];
    const float* Wg    = (const float*)d_in[1];
    const float* bg    = (const float*)d_in[2];
    const float* Wt    = (const float*)d_in[3];
    const float* bt    = (const float*)d_in[4];
    const float* Wp    = (const float*)d_in[5];
    const float* bp    = (const float*)d_in[6];
    const float* Wf    = (const float*)d_in[7];
    const float* bf    = (const float*)d_in[8];
    const float* Wz    = (const float*)d_in[9];
    const float* bz    = (const float*)d_in[10];
    const float* gamma = (const float*)d_in[11];
    const float* beta  = (const float*)d_in[12];
    const float* W3    = (const float*)d_in[13];
    float* out = (float*)d_out;

    k1_stream<<<Bq * CHUNKS, 256>>>(x, W3, out);
    kpool<<<Bq, 1024>>>();
    kproj<<<24, 256>>>(Wg, bg, Wt, bt, Wp, bp);
    kwy<<<Bq, 256>>>(Wf, bf, Wz, bz);
    kbn_topk<<<1, 512>>>(gamma, beta);
    kgather<<<Bq * 3, 1024>>>(x, out);
}

// round 14
// speedup vs baseline: 2.7713x; 1.0060x over previous
#include <cuda_runtime.h>
#include <cstdint>
#include <math.h>

#define Bq     16
#define Cq     256
#define HWq    16384
#define INTERq 128
#define CHUNKS 128               // pixel chunks per sample (128 px each)

// scratch
__device__ float g_csum[Bq * CHUNKS * Cq];  // [b][chunk][c] partial channel sums (2 MB)
__device__ float g_pt  [Cq * Bq];           // pooled means TRANSPOSED [c][b]
__device__ float g_gtp [384 * Bq];          // proj outputs [col][b]: g|theta|phi
__device__ float g_wyt [Cq * Bq];           // pre-BN activations [c][b]
__device__ int   g_idx [Bq * 3];            // top-3 channels per sample
__device__ int   g_done;                    // kwy completion counter

__device__ __forceinline__ float gelu_exact(float v) {
    return 0.5f * v * (1.0f + erff(v * 0.70710678118654752f));
}

// ---------------------------------------------------------------------------
// K1 (R4-exact, proven 45.6us @ 75.8% DRAM): single streaming pass over x.
// ---------------------------------------------------------------------------
__global__ __launch_bounds__(256) void k1_stream(const float* __restrict__ x,
                                                 const float* __restrict__ W3,
                                                 float* __restrict__ out) {
    __shared__ float sw[Cq];
    __shared__ float scs[Cq][8];        // [channel][pw]   : 8 KB
    __shared__ float sdot[4][32][32];   // [seg][cw][pix%32]: 16 KB

    const int b     = blockIdx.x >> 7;
    const int chunk = blockIdx.x & 127;
    const int t  = threadIdx.x;
    const int cw = t >> 3;              // 0..31 channel group
    const int pw = t & 7;               // 0..7 pixel slot

    for (int i = t; i < Cq; i += 256) sw[i] = W3[i];
    __syncthreads();

    const float* xb = x + ((size_t)b * Cq + (size_t)cw * 8) * HWq
                        + (size_t)chunk * 128 + (size_t)pw * 4;

    float4 dot[4];
    #pragma unroll
    for (int s = 0; s < 4; ++s) dot[s] = make_float4(0.f, 0.f, 0.f, 0.f);
    float cs[8];
    #pragma unroll
    for (int j = 0; j < 8; ++j) cs[j] = 0.f;

    #pragma unroll
    for (int j = 0; j < 8; ++j) {
        const float w = sw[cw * 8 + j];
        const float* xc = xb + (size_t)j * HWq;
        #pragma unroll
        for (int s = 0; s < 4; ++s) {
            const float4 v = *reinterpret_cast<const float4*>(xc + s * 32);
            dot[s].x = fmaf(v.x, w, dot[s].x);
            dot[s].y = fmaf(v.y, w, dot[s].y);
            dot[s].z = fmaf(v.z, w, dot[s].z);
            dot[s].w = fmaf(v.w, w, dot[s].w);
            cs[j] += (v.x + v.y) + (v.z + v.w);
        }
    }

    #pragma unroll
    for (int j = 0; j < 8; ++j) scs[cw * 8 + j][pw] = cs[j];
    #pragma unroll
    for (int s = 0; s < 4; ++s)
        *reinterpret_cast<float4*>(&sdot[s][cw][pw * 4]) = dot[s];
    __syncthreads();

    {
        float s = 0.f;
        #pragma unroll
        for (int k = 0; k < 8; ++k) s += scs[t][k];
        g_csum[((size_t)b * CHUNKS + chunk) * Cq + t] = s;
    }

    if (t < 128) {
        const int s = t >> 5, q = t & 31;
        float d = 0.f;
        #pragma unroll
        for (int k = 0; k < 32; ++k) d += sdot[s][k][q];
        out[(size_t)b * 4 * HWq + (size_t)chunk * 128 + t] = gelu_exact(d);
    }
}

// ---------------------------------------------------------------------------
// KPOOL (R12-proven): 16 blocks x 1024 threads.
// ---------------------------------------------------------------------------
__global__ __launch_bounds__(1024) void kpool() {
    __shared__ float part[4][Cq];
    const int b  = blockIdx.x;
    const int t  = threadIdx.x;
    const int c  = t & 255;
    const int qq = t >> 8;

    const float* cs = g_csum + (size_t)b * CHUNKS * Cq + (size_t)qq * 32 * Cq + c;
    float s = 0.f;
    #pragma unroll 8
    for (int k = 0; k < 32; ++k) s += cs[(size_t)k * Cq];
    part[qq][c] = s;
    __syncthreads();
    if (t < Cq)
        g_pt[t * Bq + b] = ((part[0][t] + part[1][t]) + (part[2][t] + part[3][t]))
                         * (1.0f / (float)HWq);
}

// ---------------------------------------------------------------------------
// KPROJ (R13-proven): 24 blocks x 256; block = 16 of 384 columns.
//   Also resets g_done (block 0) — stream-ordered before kwy_bn.
// ---------------------------------------------------------------------------
__global__ __launch_bounds__(256) void kproj(
    const float* __restrict__ Wg, const float* __restrict__ bg,
    const float* __restrict__ Wt, const float* __restrict__ bt,
    const float* __restrict__ Wp, const float* __restrict__ bp)
{
    __shared__ float sp_t[Cq * Bq];    // 16 KB [i][b]
    __shared__ float swt[16][Cq];      // 16 KB
    __shared__ float sb[16];

    const int t    = threadIdx.x;
    const int col0 = blockIdx.x * 16;

    if (blockIdx.x == 0 && t == 0) g_done = 0;

    #pragma unroll
    for (int j = 0; j < 4; ++j)
        reinterpret_cast<float4*>(sp_t)[j * 256 + t] =
            reinterpret_cast<const float4*>(g_pt)[j * 256 + t];

    #pragma unroll
    for (int j = 0; j < 4; ++j) {
        const int id = j * 256 + t;           // float4 id
        const int r  = id >> 6;               // row 0..15
        const int c4 = id & 63;
        const int col = col0 + r;
        const int cg  = col >> 7;
        const int lc  = col & 127;
        const float* Wrow = (cg == 0) ? (Wg + (size_t)lc * Cq)
                          : (cg == 1) ? (Wt + (size_t)lc * Cq)
                                      : (Wp + (size_t)lc * Cq);
        reinterpret_cast<float4*>(&swt[r][0])[c4] =
            reinterpret_cast<const float4*>(Wrow)[c4];
    }
    if (t < 16) {
        const int col = col0 + t;
        const int cg  = col >> 7;
        const int lc  = col & 127;
        sb[t] = (cg == 0) ? bg[lc] : (cg == 1) ? bt[lc] : bp[lc];
    }
    __syncthreads();

    const int b    = t & 15;          // batch
    const int slot = t >> 4;          // 0..15 column slot
    float a0 = 0.f, a1 = 0.f, a2 = 0.f, a3 = 0.f;
    #pragma unroll 8
    for (int i = 0; i < Cq; i += 4) {
        a0 = fmaf(swt[slot][i + 0], sp_t[(i + 0) * Bq + b], a0);
        a1 = fmaf(swt[slot][i + 1], sp_t[(i + 1) * Bq + b], a1);
        a2 = fmaf(swt[slot][i + 2], sp_t[(i + 2) * Bq + b], a2);
        a3 = fmaf(swt[slot][i + 3], sp_t[(i + 3) * Bq + b], a3);
    }
    g_gtp[(col0 + slot) * Bq + b] = ((a0 + a1) + (a2 + a3)) + sb[slot];
}

// ---------------------------------------------------------------------------
// KWY_BN: 16 blocks x 256 threads; block = 16 Wz columns.
//   f parallelized: 256 threads compute 16-element partials, 16 finalize.
//   Last finisher block fuses BN over batch + top-3 (reuses stp as sz).
// ---------------------------------------------------------------------------
__global__ __launch_bounds__(256) void kwy_bn(
    const float* __restrict__ Wf, const float* __restrict__ bf,
    const float* __restrict__ Wz, const float* __restrict__ bz,
    const float* __restrict__ gamma, const float* __restrict__ beta)
{
    __shared__ float sg_t[INTERq * Bq];      // 8 KB [i][b]
    __shared__ float stp [2 * INTERq * Bq];  // 16 KB [i][b] (th|ph); reused as sz
    __shared__ float swz[16][INTERq];        // 8 KB
    __shared__ float swf[2 * INTERq];        // 1 KB
    __shared__ float sfp[16][16];            // f partials [slot][b]
    __shared__ float sf[Bq];
    __shared__ float sbz[16];
    __shared__ int   s_last;

    const int t    = threadIdx.x;
    const int col0 = blockIdx.x * 16;
    const int b    = t & 15;
    const int slot = t >> 4;

    if (t == 0) s_last = 0;

    #pragma unroll
    for (int j = 0; j < 2; ++j)
        reinterpret_cast<float4*>(sg_t)[j * 256 + t] =
            reinterpret_cast<const float4*>(g_gtp)[j * 256 + t];
    #pragma unroll
    for (int j = 0; j < 4; ++j)
        reinterpret_cast<float4*>(stp)[j * 256 + t] =
            reinterpret_cast<const float4*>(g_gtp + 2048)[j * 256 + t];
    #pragma unroll
    for (int j = 0; j < 2; ++j) {
        const int id = j * 256 + t;          // float4 id
        const int r  = id >> 5;              // row 0..15
        const int c4 = id & 31;
        reinterpret_cast<float4*>(&swz[r][0])[c4] =
            reinterpret_cast<const float4*>(Wz + (size_t)(col0 + r) * INTERq)[c4];
    }
    swf[t] = Wf[t];
    if (t < 16) sbz[t] = bz[col0 + t];
    __syncthreads();

    // f partials: thread (slot,b) covers elements [slot*16, slot*16+16)
    {
        float a = 0.f;
        #pragma unroll
        for (int i = 0; i < 16; ++i) {
            const int e = slot * 16 + i;
            a = fmaf(stp[e * Bq + b], swf[e], a);
        }
        sfp[slot][b] = a;
    }
    __syncthreads();
    if (t < 16) {
        float s0 = 0.f, s1 = 0.f;
        #pragma unroll
        for (int k = 0; k < 16; k += 2) { s0 += sfp[k][t]; s1 += sfp[k + 1][t]; }
        sf[t] = fmaxf(s0 + s1 + bf[0], 0.f);
    }

    // main dot (independent of f until the end)
    float a0 = 0.f, a1 = 0.f, a2 = 0.f, a3 = 0.f;
    #pragma unroll 8
    for (int i = 0; i < INTERq; i += 4) {
        a0 = fmaf(swz[slot][i + 0], sg_t[(i + 0) * Bq + b], a0);
        a1 = fmaf(swz[slot][i + 1], sg_t[(i + 1) * Bq + b], a1);
        a2 = fmaf(swz[slot][i + 2], sg_t[(i + 2) * Bq + b], a2);
        a3 = fmaf(swz[slot][i + 3], sg_t[(i + 3) * Bq + b], a3);
    }
    __syncthreads();
    g_wyt[(col0 + slot) * Bq + b] = fmaf(sf[b], ((a0 + a1) + (a2 + a3)), sbz[slot]);

    // ---- last-block-done: BN + top-3 ----
    __threadfence();
    __syncthreads();
    if (t == 0) {
        const int old = atomicAdd(&g_done, 1);
        if (old == 15) s_last = 1;
    }
    __syncthreads();
    if (!s_last) return;
    __threadfence();   // acquire other blocks' g_wyt

    float* sz = stp;   // reuse 16 KB as z [b][c]

    {   // BN per channel c = t (coalesced float4 reads of [c][b] rows)
        const int c = t;
        float vals[Bq];
        const float4* w4 = reinterpret_cast<const float4*>(g_wyt + c * Bq);
        const float4* p4 = reinterpret_cast<const float4*>(g_pt  + c * Bq);
        #pragma unroll
        for (int k = 0; k < 4; ++k) {
            const float4 v = w4[k];
            vals[k * 4 + 0] = v.x; vals[k * 4 + 1] = v.y;
            vals[k * 4 + 2] = v.z; vals[k * 4 + 3] = v.w;
        }
        float m = 0.f;
        #pragma unroll
        for (int bb = 0; bb < Bq; ++bb) m += vals[bb];
        m *= (1.0f / (float)Bq);
        float var = 0.f;
        #pragma unroll
        for (int bb = 0; bb < Bq; ++bb) { const float d = vals[bb] - m; var = fmaf(d, d, var); }
        var *= (1.0f / (float)Bq);
        const float inv = rsqrtf(var + 1e-5f);
        const float ga = gamma[c], be = beta[c];
        #pragma unroll
        for (int k = 0; k < 4; ++k) {
            const float4 p = p4[k];
            sz[(k * 4 + 0) * Cq + c] = fmaf(ga * (vals[k * 4 + 0] - m), inv, be) + p.x;
            sz[(k * 4 + 1) * Cq + c] = fmaf(ga * (vals[k * 4 + 1] - m), inv, be) + p.y;
            sz[(k * 4 + 2) * Cq + c] = fmaf(ga * (vals[k * 4 + 2] - m), inv, be) + p.z;
            sz[(k * 4 + 3) * Cq + c] = fmaf(ga * (vals[k * 4 + 3] - m), inv, be) + p.w;
        }
    }
    __syncthreads();

    // top-3: 8 warps, each handles samples warp and warp+8
    {
        const int warp = t >> 5;
        const int lane = t & 31;
        #pragma unroll
        for (int sb2 = 0; sb2 < 2; ++sb2) {
            const int smp = warp + sb2 * 8;
            float v[8];
            const int base = smp * Cq;
            #pragma unroll
            for (int k = 0; k < 8; ++k) v[k] = sz[base + k * 32 + lane];

            for (int j = 0; j < 3; ++j) {
                float bv = -INFINITY;
                int   bi = 0x7fffffff;
                #pragma unroll
                for (int k = 0; k < 8; ++k) {
                    const int idx = k * 32 + lane;
                    if (v[k] > bv) { bv = v[k]; bi = idx; }
                }
                #pragma unroll
                for (int off = 16; off > 0; off >>= 1) {
                    const float ov = __shfl_down_sync(0xffffffffu, bv, off);
                    const int   oi = __shfl_down_sync(0xffffffffu, bi, off);
                    if (ov > bv || (ov == bv && oi < bi)) { bv = ov; bi = oi; }
                }
                bi = __shfl_sync(0xffffffffu, bi, 0);
                if (lane == 0) g_idx[smp * 3 + j] = bi;
                const int kk = bi >> 5;
                if ((bi & 31) == lane) {
                    #pragma unroll
                    for (int k = 0; k < 8; ++k) if (k == kk) v[k] = -INFINITY;
                }
            }
        }
    }
}

// ---------------------------------------------------------------------------
// KGATHER (R10-proven): 48 blocks x 1024; 4 float4 per thread.
// ---------------------------------------------------------------------------
__global__ __launch_bounds__(1024) void kgather(const float* __restrict__ x,
                                                float* __restrict__ out) {
    const int b = blockIdx.x / 3, j = blockIdx.x % 3;
    const int ch = g_idx[b * 3 + j];
    const float* src = x + ((size_t)b * Cq + ch) * HWq;
    float* dst = out + ((size_t)b * 4 + 1 + j) * HWq;
    const int t = threadIdx.x;
    const float4 v0 = *reinterpret_cast<const float4*>(src + t * 4);
    const float4 v1 = *reinterpret_cast<const float4*>(src + 4096 + t * 4);
    const float4 v2 = *reinterpret_cast<const float4*>(src + 8192 + t * 4);
    const float4 v3 = *reinterpret_cast<const float4*>(src + 12288 + t * 4);
    *reinterpret_cast<float4*>(dst + t * 4)         = v0;
    *reinterpret_cast<float4*>(dst + 4096 + t * 4)  = v1;
    *reinterpret_cast<float4*>(dst + 8192 + t * 4)  = v2;
    *reinterpret_cast<float4*>(dst + 12288 + t * 4) = v3;
}

extern "C" void kernel_launch(void* const* d_in, const int* in_sizes, int n_in,
                              void* d_out, int out_size) {
    const float* x     = (const float*)d_in[0];
    const float* Wg    = (const float*)d_in[1];
    const float* bg    = (const float*)d_in[2];
    const float* Wt    = (const float*)d_in[3];
    const float* bt    = (const float*)d_in[4];
    const float* Wp    = (const float*)d_in[5];
    const float* bp    = (const float*)d_in[6];
    const float* Wf    = (const float*)d_in[7];
    const float* bf    = (const float*)d_in[8];
    const float* Wz    = (const float*)d_in[9];
    const float* bz    = (const float*)d_in[10];
    const float* gamma = (const float*)d_in[11];
    const float* beta  = (const float*)d_in[12];
    const float* W3    = (const float*)d_in[13];
    float* out = (float*)d_out;

    k1_stream<<<Bq * CHUNKS, 256>>>(x, W3, out);
    kpool<<<Bq, 1024>>>();
    kproj<<<24, 256>>>(Wg, bg, Wt, bt, Wp, bp);
    kwy_bn<<<Bq, 256>>>(Wf, bf, Wz, bz, gamma, beta);
    kgather<<<Bq * 3, 1024>>>(x, out);
}